// round 7
// baseline (speedup 1.0000x reference)
#include <cuda_runtime.h>

#define CA_EPS  1e-8f
#define CA_K    512
#define CA_FF   16          // F*F
#define CA_HALF 8192        // K*FF : x-flat per batch / xc-half offset in W row
#define CA_FEAT 16384       // 2*K*FF : W row length
#define SLICE   16
#define NT      512
#define GRID    64

__device__ float4   g_accum;      // zero at entry; restored to zero every call
__device__ unsigned g_count;      // zero at entry; restored to zero every call

// grid = 64 (32 slice-CTAs per batch), block = 512 (one thread per channel for
// phases 1-2; one warp per slice-channel for phases 3-4).
__global__ __launch_bounds__(NT, 1)
void ca_fused(const float* __restrict__ x, const float* __restrict__ W,
              const float* __restrict__ bias, float* __restrict__ out) {
    const int b    = blockIdx.x >> 5;            // batch (0..1)
    const int c0   = (blockIdx.x & 31) * SLICE;  // slice start channel
    const int tid  = threadIdx.x;
    const int lane = tid & 31, warp = tid >> 5;

    __shared__ unsigned s_red[16];
    __shared__ float s_D[CA_K];

    // ---- early prefetch: bias (for the tail) -------------------------------
    float bias0 = 0.f, bias1 = 0.f;
    if (tid == 0) { bias0 = __ldg(bias); bias1 = __ldg(bias + 1); }

    // ---- prefetch matvec operands: warp w owns channel c0+w ----------------
    // lane: cls = lane>>4 (class), fi = lane&15 (element within channel)
    const int cls = lane >> 4;
    const int fi  = lane & 15;
    const int ch  = c0 + warp;
    const float xm = __ldg(x + (size_t)b * CA_HALF + (size_t)ch * CA_FF + fi);
    const float* wrow = W + (size_t)cls * CA_FEAT + (size_t)ch * CA_FF + fi;
    const float wa = __ldg(wrow);
    const float wb = __ldg(wrow + CA_HALF);

    // ---- load own channel (k = tid): 4 contiguous float4 -------------------
    const float4* xp = reinterpret_cast<const float4*>(x + (size_t)b * CA_HALF) + (size_t)tid * 4;
    float4 a0 = xp[0], a1 = xp[1], a2 = xp[2], a3 = xp[3];

    // ---- phase 1: per-batch global max -------------------------------------
    // x is post-ReLU (>= 0): float max == uint max on bit patterns -> REDUX.
    float m = fmaxf(fmaxf(fmaxf(a0.x, a0.y), fmaxf(a0.z, a0.w)),
                    fmaxf(fmaxf(a1.x, a1.y), fmaxf(a1.z, a1.w)));
    m = fmaxf(m, fmaxf(fmaxf(fmaxf(a2.x, a2.y), fmaxf(a2.z, a2.w)),
                       fmaxf(fmaxf(a3.x, a3.y), fmaxf(a3.z, a3.w))));
    unsigned mu = __reduce_max_sync(0xFFFFFFFFu, __float_as_uint(m));
    if (lane == 0) s_red[warp] = mu;
    __syncthreads();
    // second level: one broadcast-safe LDS + one REDUX (per warp)
    unsigned mmu = __reduce_max_sync(0xFFFFFFFFu, s_red[lane & 15]);
    const float inv = 1.0f / (__uint_as_float(mmu) + CA_EPS);

    // ---- phase 2: lehmer_den D for the own channel -------------------------
    {
        float s1 = 0.f, s2 = 0.f, t;
        t = a0.x * inv + CA_EPS; s1 += t; s2 += t * t;
        t = a0.y * inv + CA_EPS; s1 += t; s2 += t * t;
        t = a0.z * inv + CA_EPS; s1 += t; s2 += t * t;
        t = a0.w * inv + CA_EPS; s1 += t; s2 += t * t;
        t = a1.x * inv + CA_EPS; s1 += t; s2 += t * t;
        t = a1.y * inv + CA_EPS; s1 += t; s2 += t * t;
        t = a1.z * inv + CA_EPS; s1 += t; s2 += t * t;
        t = a1.w * inv + CA_EPS; s1 += t; s2 += t * t;
        t = a2.x * inv + CA_EPS; s1 += t; s2 += t * t;
        t = a2.y * inv + CA_EPS; s1 += t; s2 += t * t;
        t = a2.z * inv + CA_EPS; s1 += t; s2 += t * t;
        t = a2.w * inv + CA_EPS; s1 += t; s2 += t * t;
        t = a3.x * inv + CA_EPS; s1 += t; s2 += t * t;
        t = a3.y * inv + CA_EPS; s1 += t; s2 += t * t;
        t = a3.z * inv + CA_EPS; s1 += t; s2 += t * t;
        t = a3.w * inv + CA_EPS; s1 += t; s2 += t * t;
        s_D[tid] = (s2 + CA_EPS) / (s1 + CA_EPS) + CA_EPS;
    }
    __syncthreads();

    // ---- phase 3+4 fused: warp w handles slice channel c0+w ----------------
    // bool[m,n] decision reduces to sign(D[m]-D[n]); fac = relu(wins-losses).
    // reduce_add leaves wl in ALL lanes -> fac known in-warp, no smem/bar.
    {
        const float Dk = s_D[ch];               // broadcast (all lanes same addr)
        int wl = 0;
        #pragma unroll
        for (int i = 0; i < 16; ++i) {          // conflict-free: stride-1 by lane
            float d = s_D[i * 32 + lane];
            wl += (Dk > d) - (d > Dk);
        }
        wl = __reduce_add_sync(0xFFFFFFFFu, wl);
        const float fac = fmaxf((float)wl, 0.0f);

        // matvec contribution of channel ch for class cls (16-lane segments)
        float p = xm * fmaf(fac, wb, wa);
        p += __shfl_xor_sync(0xFFFFFFFFu, p, 8);
        p += __shfl_xor_sync(0xFFFFFFFFu, p, 4);
        p += __shfl_xor_sync(0xFFFFFFFFu, p, 2);
        p += __shfl_xor_sync(0xFFFFFFFFu, p, 1);
        if (fi == 0) {                          // lanes 0 and 16: REDG, no return
            float* acc = reinterpret_cast<float*>(&g_accum);
            atomicAdd(acc + (b * 2 + cls), p);
        }
    }
    __syncthreads();   // cta-scope: orders all 32 REDs before the ticket

    // ---- last-CTA finalize (restores scratch to zero for next call) --------
    if (tid == 0) {
        // acq_rel gpu-scope ticket: cumulative release publishes this CTA's
        // REDs (ordered by the bar.sync above) without MEMBAR.GPU.
        unsigned ticket;
        asm volatile("atom.acq_rel.gpu.global.add.u32 %0, [%1], 1;"
                     : "=r"(ticket) : "l"(&g_count) : "memory");
        if (ticket == GRID - 1) {
            // all 64 tickets in => all REDs visible at L2
            float4 r;
            asm volatile("ld.global.cg.v4.f32 {%0,%1,%2,%3}, [%4];"
                         : "=f"(r.x), "=f"(r.y), "=f"(r.z), "=f"(r.w)
                         : "l"(&g_accum) : "memory");
            float4 res = make_float4(bias0 + r.x, bias1 + r.y,
                                     bias0 + r.z, bias1 + r.w);
            *reinterpret_cast<float4*>(out) = res;
            asm volatile("st.global.cg.v4.f32 [%0], {%1,%2,%3,%4};"
                         :: "l"(&g_accum), "f"(0.f), "f"(0.f), "f"(0.f), "f"(0.f)
                         : "memory");
            __stcg(&g_count, 0u);
        }
    }
}

extern "C" void kernel_launch(void* const* d_in, const int* in_sizes, int n_in,
                              void* d_out, int out_size) {
    const float* x    = (const float*)d_in[0];   // [2, 512, 4, 4]
    const float* W    = (const float*)d_in[1];   // [2, 16384]
    const float* bias = (const float*)d_in[2];   // [2]
    float* out = (float*)d_out;                  // [2, 2]
    ca_fused<<<GRID, NT>>>(x, W, bias, out);
}